// round 11
// baseline (speedup 1.0000x reference)
#include <cuda_runtime.h>
#include <cuda_bf16.h>

// Problem geometry (fixed by the dataset).
static constexpr int Dv = 160;
static constexpr int Hv = 192;
static constexpr int Wv = 160;
static constexpr int SH = Wv;           // stride of one h-row
static constexpr int SD = Hv * Wv;      // stride of one d-slice (30720)
static constexpr int V  = Dv * Hv * Wv; // 4,915,200 voxels
static constexpr int HALF = V / 2;      // threads (2 consecutive-x voxels each)

// Affine fold constants (double-evaluated, rounded to fp32).
// Stage B:  j = (coord + of*rf) * (S/(S-1)) - 0.5
static constexpr float CW = (float)(160.0 / 159.0);
static constexpr float CH = (float)(192.0 / 191.0);
static constexpr float CD = (float)(160.0 / 159.0);
// Stage A:  i = ((g+1)*S - 1) * 0.5 = g*(S/2) + (S-1)/2
static constexpr float AW = 80.0f,  BW = 79.5f;
static constexpr float AH = 96.0f,  BH = 95.5f;
static constexpr float AD = 80.0f,  BD = 79.5f;

// ---------------------------------------------------------------------------
// Prep phase of the src trilinear sample: interior test, base offset and the
// 8 folded corner weights. Returns false on the (rare) boundary case; the
// base offset is only meaningful when true.
// ---------------------------------------------------------------------------
__device__ __forceinline__ bool prep_src(float ix, float iy, float iz,
                                         int& base,
                                         float& w0, float& w1, float& w2, float& w3,
                                         float& w4, float& w5, float& w6, float& w7) {
    float xf = floorf(ix), yf = floorf(iy), zf = floorf(iz);
    float tx = ix - xf,    ty = iy - yf,    tz = iz - zf;
    int   x0 = (int)xf,    y0 = (int)yf,    z0 = (int)zf;

    float wx0 = 1.0f - tx, wy0 = 1.0f - ty, wz0 = 1.0f - tz;
    float a = wz0 * wy0;   // z0,y0
    float b = wz0 * ty;    // z0,y1
    float c = tz  * wy0;   // z1,y0
    float e = tz  * ty;    // z1,y1

    w0 = a * wx0; w1 = a * tx;
    w2 = b * wx0; w3 = b * tx;
    w4 = c * wx0; w5 = c * tx;
    w6 = e * wx0; w7 = e * tx;

    base = (z0 * Hv + y0) * Wv + x0;

    bool in = ((unsigned)x0       < (unsigned)Wv) &
              ((unsigned)(x0 + 1) < (unsigned)Wv) &
              ((unsigned)y0       < (unsigned)Hv) &
              ((unsigned)(y0 + 1) < (unsigned)Hv) &
              ((unsigned)z0       < (unsigned)Dv) &
              ((unsigned)(z0 + 1) < (unsigned)Dv);
    return in;
}

// ---------------------------------------------------------------------------
// Full (boundary-capable) trilinear sample of src, zeros padding. Used only
// on the rare boundary path. Reference-equivalent clamp + mask formulation.
// ---------------------------------------------------------------------------
__device__ __noinline__ float samp_src_slow(const float* __restrict__ v,
                                            float ix, float iy, float iz) {
    float xf = floorf(ix), yf = floorf(iy), zf = floorf(iz);
    float tx = ix - xf,    ty = iy - yf,    tz = iz - zf;
    int   x0 = (int)xf,    y0 = (int)yf,    z0 = (int)zf;

    float wx0 = 1.0f - tx, wy0 = 1.0f - ty, wz0 = 1.0f - tz;
    float a = wz0 * wy0, b = wz0 * ty, c = tz * wy0, e = tz * ty;

    bool bx0 = (unsigned)x0       < (unsigned)Wv;
    bool bx1 = (unsigned)(x0 + 1) < (unsigned)Wv;
    bool by0 = (unsigned)y0       < (unsigned)Hv;
    bool by1 = (unsigned)(y0 + 1) < (unsigned)Hv;
    bool bz0 = (unsigned)z0       < (unsigned)Dv;
    bool bz1 = (unsigned)(z0 + 1) < (unsigned)Dv;

    int cx0 = min(max(x0,     0), Wv - 1), cx1 = min(max(x0 + 1, 0), Wv - 1);
    int cy0 = min(max(y0,     0), Hv - 1), cy1 = min(max(y0 + 1, 0), Hv - 1);
    int cz0 = min(max(z0,     0), Dv - 1), cz1 = min(max(z0 + 1, 0), Dv - 1);

    float acc = 0.0f;
    acc += v[(cz0 * Hv + cy0) * Wv + cx0] * ((a * wx0) * ((bz0 & by0 & bx0) ? 1.0f : 0.0f));
    acc += v[(cz0 * Hv + cy0) * Wv + cx1] * ((a * tx ) * ((bz0 & by0 & bx1) ? 1.0f : 0.0f));
    acc += v[(cz0 * Hv + cy1) * Wv + cx0] * ((b * wx0) * ((bz0 & by1 & bx0) ? 1.0f : 0.0f));
    acc += v[(cz0 * Hv + cy1) * Wv + cx1] * ((b * tx ) * ((bz0 & by1 & bx1) ? 1.0f : 0.0f));
    acc += v[(cz1 * Hv + cy0) * Wv + cx0] * ((c * wx0) * ((bz1 & by0 & bx0) ? 1.0f : 0.0f));
    acc += v[(cz1 * Hv + cy0) * Wv + cx1] * ((c * tx ) * ((bz1 & by0 & bx1) ? 1.0f : 0.0f));
    acc += v[(cz1 * Hv + cy1) * Wv + cx0] * ((e * wx0) * ((bz1 & by1 & bx0) ? 1.0f : 0.0f));
    acc += v[(cz1 * Hv + cy1) * Wv + cx1] * ((e * tx ) * ((bz1 & by1 & bx1) ? 1.0f : 0.0f));
    return acc;
}

// ---------------------------------------------------------------------------
// Trilinear sample of the 3-channel flow1 volume, zeros padding. The
// reference feeds RAW voxel coordinates through the [-1,1] unnormalizer, so
// this is fully out of bounds for essentially every voxel. Caller does the
// cheap fully-out test; this is the rare slow path (out of line so its
// registers don't bloat the hot path).
// ---------------------------------------------------------------------------
__device__ __noinline__ void samp_flow(const float* __restrict__ f,
                                       float ix, float iy, float iz,
                                       float& o0, float& o1, float& o2) {
    float xf = floorf(ix), yf = floorf(iy), zf = floorf(iz);
    int   x0 = (int)xf,    y0 = (int)yf,    z0 = (int)zf;

    float tx = ix - xf, ty = iy - yf, tz = iz - zf;
    float wx0 = 1.0f - tx, wy0 = 1.0f - ty, wz0 = 1.0f - tz;
    float a = wz0 * wy0, b = wz0 * ty, c = tz * wy0, e = tz * ty;

    bool bx0 = (unsigned)x0       < (unsigned)Wv;
    bool bx1 = (unsigned)(x0 + 1) < (unsigned)Wv;
    bool by0 = (unsigned)y0       < (unsigned)Hv;
    bool by1 = (unsigned)(y0 + 1) < (unsigned)Hv;
    bool bz0 = (unsigned)z0       < (unsigned)Dv;
    bool bz1 = (unsigned)(z0 + 1) < (unsigned)Dv;

    int cx0 = min(max(x0,     0), Wv - 1), cx1 = min(max(x0 + 1, 0), Wv - 1);
    int cy0 = min(max(y0,     0), Hv - 1), cy1 = min(max(y0 + 1, 0), Hv - 1);
    int cz0 = min(max(z0,     0), Dv - 1), cz1 = min(max(z0 + 1, 0), Dv - 1);

    int   idx[8];
    float wgt[8];
    idx[0] = (cz0 * Hv + cy0) * Wv + cx0; wgt[0] = (a * wx0) * ((bz0 & by0 & bx0) ? 1.0f : 0.0f);
    idx[1] = (cz0 * Hv + cy0) * Wv + cx1; wgt[1] = (a * tx ) * ((bz0 & by0 & bx1) ? 1.0f : 0.0f);
    idx[2] = (cz0 * Hv + cy1) * Wv + cx0; wgt[2] = (b * wx0) * ((bz0 & by1 & bx0) ? 1.0f : 0.0f);
    idx[3] = (cz0 * Hv + cy1) * Wv + cx1; wgt[3] = (b * tx ) * ((bz0 & by1 & bx1) ? 1.0f : 0.0f);
    idx[4] = (cz1 * Hv + cy0) * Wv + cx0; wgt[4] = (c * wx0) * ((bz1 & by0 & bx0) ? 1.0f : 0.0f);
    idx[5] = (cz1 * Hv + cy0) * Wv + cx1; wgt[5] = (c * tx ) * ((bz1 & by0 & bx1) ? 1.0f : 0.0f);
    idx[6] = (cz1 * Hv + cy1) * Wv + cx0; wgt[6] = (e * wx0) * ((bz1 & by1 & bx0) ? 1.0f : 0.0f);
    idx[7] = (cz1 * Hv + cy1) * Wv + cx1; wgt[7] = (e * tx ) * ((bz1 & by1 & bx1) ? 1.0f : 0.0f);

    float s0 = 0.f, s1 = 0.f, s2 = 0.f;
#pragma unroll
    for (int k = 0; k < 8; k++) {
        float wk = wgt[k];
        int   ik = idx[k];
        s0 += f[ik]         * wk;
        s1 += f[V + ik]     * wk;
        s2 += f[2 * V + ik] * wk;
    }
    o0 = s0; o1 = s1; o2 = s2;
}

// ---------------------------------------------------------------------------
// Fused kernel: 2 consecutive-x voxels per thread (p = 2t, 2t+1).
// Phase order: flow2 loads -> stage A -> out_flow STORES (retire regs early)
// -> stage B coords -> prep both voxels -> 16 BATCHED gathers -> dot -> store.
// The batched-gather fast path covers the interior/interior case (~90% of
// warps, nearly warp-uniform); it exposes one L2 round-trip per PAIR instead
// of per voxel.
//   out[0 : V ) = deform_2_img
//   out[V : 2V) = out_flow ch0 (d)
//   out[2V: 3V) = out_flow ch1 (h)
//   out[3V: 4V) = out_flow ch2 (w)
// ---------------------------------------------------------------------------
__global__ void __launch_bounds__(256, 5)
spatial_transformer_pair(const float* __restrict__ src,
                         const float* __restrict__ flow1,
                         const float* __restrict__ flow2,
                         const float* __restrict__ rf_ptr,
                         float* __restrict__ out) {
    int t = blockIdx.x * blockDim.x + threadIdx.x;   // 0 .. HALF-1
    const float rf = __ldg(rf_ptr);

    const int p = 2 * t;              // even voxel index
    int w = p % Wv;                   // even, pair stays in-row
    int r = p / Wv;
    int h = r % Hv;
    int d = r / Hv;

    const float fw_ = (float)w;
    const float fh_ = (float)h;
    const float fd_ = (float)d;

    // Vectorized flow2 loads (8B-aligned: p even, V even).
    float2 F2d = *reinterpret_cast<const float2*>(flow2 + p);
    float2 F2h = *reinterpret_cast<const float2*>(flow2 + V + p);
    float2 F2w = *reinterpret_cast<const float2*>(flow2 + 2 * V + p);

    // ---- Stage A (both voxels): raw voxel coords through the [-1,1]
    // unnormalizer (bug-compatible): i = g*S/2 + (S-1)/2. Almost always
    // fully out of bounds -> zero.
    float of[6]; // ofd0, ofd1, ofh0, ofh1, ofw0, ofw1
    {
        float gz0 = fmaf(F2d.x, rf, fd_), gz1 = fmaf(F2d.y, rf, fd_);
        float gy0 = fmaf(F2h.x, rf, fh_), gy1 = fmaf(F2h.y, rf, fh_);
        float gx0 = fmaf(F2w.x, rf, fw_), gx1 = fmaf(F2w.y, rf, fw_ + 1.0f);

        float ix0 = fmaf(gx0, AW, BW), ix1 = fmaf(gx1, AW, BW);
        float iy0 = fmaf(gy0, AH, BH), iy1 = fmaf(gy1, AH, BH);
        float iz0 = fmaf(gz0, AD, BD), iz1 = fmaf(gz1, AD, BD);

        float a0 = 0.f, a1 = 0.f, a2 = 0.f;
        if (!(ix0 < -1.0f || ix0 >= (float)Wv ||
              iy0 < -1.0f || iy0 >= (float)Hv ||
              iz0 < -1.0f || iz0 >= (float)Dv))
            samp_flow(flow1, ix0, iy0, iz0, a0, a1, a2);

        float b0 = 0.f, b1 = 0.f, b2 = 0.f;
        if (!(ix1 < -1.0f || ix1 >= (float)Wv ||
              iy1 < -1.0f || iy1 >= (float)Hv ||
              iz1 < -1.0f || iz1 >= (float)Dv))
            samp_flow(flow1, ix1, iy1, iz1, b0, b1, b2);

        of[0] = a0 + F2d.x; of[1] = b0 + F2d.y;
        of[2] = a1 + F2h.x; of[3] = b1 + F2h.y;
        of[4] = a2 + F2w.x; of[5] = b2 + F2w.y;
    }

    // Retire out_flow stores NOW to free registers before the gather phase.
    *reinterpret_cast<float2*>(out + V + p)     = make_float2(of[0], of[1]);
    *reinterpret_cast<float2*>(out + 2 * V + p) = make_float2(of[2], of[3]);
    *reinterpret_cast<float2*>(out + 3 * V + p) = make_float2(of[4], of[5]);

    // ---- Stage B: folded affine  j = (coord + of*rf) * S/(S-1) - 0.5
    float jz0 = fmaf(fmaf(of[0], rf, fd_), CD, -0.5f);
    float jz1 = fmaf(fmaf(of[1], rf, fd_), CD, -0.5f);
    float jy0 = fmaf(fmaf(of[2], rf, fh_), CH, -0.5f);
    float jy1 = fmaf(fmaf(of[3], rf, fh_), CH, -0.5f);
    float jx0 = fmaf(fmaf(of[4], rf, fw_), CW, -0.5f);
    float jx1 = fmaf(fmaf(of[5], rf, fw_ + 1.0f), CW, -0.5f);

    int base0, base1;
    float u0, u1, u2, u3, u4, u5, u6, u7;   // weights voxel 0
    float q0, q1, q2, q3, q4, q5, q6, q7;   // weights voxel 1
    bool in0 = prep_src(jx0, jy0, jz0, base0, u0, u1, u2, u3, u4, u5, u6, u7);
    bool in1 = prep_src(jx1, jy1, jz1, base1, q0, q1, q2, q3, q4, q5, q6, q7);

    float img0, img1;
    if (in0 & in1) {
        const float* p0 = src + base0;
        const float* p1 = src + base1;
        // 16 independent gathers, batched back-to-back for maximal MLP.
        float v0 = p0[0],       v1 = p0[1];
        float v2 = p0[SH],      v3 = p0[SH + 1];
        float v4 = p0[SD],      v5 = p0[SD + 1];
        float v6 = p0[SD + SH], v7 = p0[SD + SH + 1];
        float s0 = p1[0],       s1 = p1[1];
        float s2 = p1[SH],      s3 = p1[SH + 1];
        float s4 = p1[SD],      s5 = p1[SD + 1];
        float s6 = p1[SD + SH], s7 = p1[SD + SH + 1];

        img0 = v0 * u0; img0 = fmaf(v1, u1, img0);
        img0 = fmaf(v2, u2, img0); img0 = fmaf(v3, u3, img0);
        img0 = fmaf(v4, u4, img0); img0 = fmaf(v5, u5, img0);
        img0 = fmaf(v6, u6, img0); img0 = fmaf(v7, u7, img0);

        img1 = s0 * q0; img1 = fmaf(s1, q1, img1);
        img1 = fmaf(s2, q2, img1); img1 = fmaf(s3, q3, img1);
        img1 = fmaf(s4, q4, img1); img1 = fmaf(s5, q5, img1);
        img1 = fmaf(s6, q6, img1); img1 = fmaf(s7, q7, img1);
    } else {
        img0 = samp_src_slow(src, jx0, jy0, jz0);
        img1 = samp_src_slow(src, jx1, jy1, jz1);
    }

    *reinterpret_cast<float2*>(out + p) = make_float2(img0, img1);
}

extern "C" void kernel_launch(void* const* d_in, const int* in_sizes, int n_in,
                              void* d_out, int out_size) {
    // metadata order: src, flow1, flow2, grid (unused: analytic meshgrid),
    // range_flow (device scalar).
    const float* src   = (const float*)d_in[0];
    const float* flow1 = (const float*)d_in[1];
    const float* flow2 = (const float*)d_in[2];
    const float* rf    = (const float*)d_in[4];
    float* out = (float*)d_out;

    const int threads = 256;
    const int blocks  = HALF / threads; // 9600
    spatial_transformer_pair<<<blocks, threads>>>(src, flow1, flow2, rf, out);
}